// round 8
// baseline (speedup 1.0000x reference)
#include <cuda_runtime.h>

#define N_NODES 50000
#define N_EDGES 800000
#define N_FEAT  256
#define N_CLASS 64

// ---------------- scratch (no allocation allowed -> device globals) ----------
__device__ int   g_cnt[N_NODES];
__device__ float g_dinv[N_NODES];
__device__ int   g_rowstart[N_NODES + 1];
__device__ int   g_cursor[N_NODES];
__device__ int   g_col[N_EDGES];
__device__ float g_val[N_EDGES];
__device__ float g_h0[(size_t)N_NODES * N_CLASS];
__device__ float g_h1[(size_t)N_NODES * N_CLASS];
__device__ int   g_idx64;

// ---------------- int64-vs-int32 edge_index detector -------------------------
// If the buffer really is int64, every sampled value is a valid node id.
// If it is int32 data read as int64, value = lo + (hi<<32) with hi a random
// node id (P(hi==0) = 1/50000), so it falls outside [0, N_NODES) essentially
// always within 256 samples.
__global__ void detect_kernel(const void* __restrict__ ei) {
    const long long* p = (const long long*)ei;
    int ok64 = 1;
    for (int i = 0; i < 256; i++) {
        long long v = p[i];
        if (v < 0 || v >= N_NODES) { ok64 = 0; break; }
    }
    g_idx64 = ok64;
}

__device__ __forceinline__ int load_idx(const void* __restrict__ ei, long i) {
    if (g_idx64) return (int)((const long long*)ei)[i];
    return ((const int*)ei)[i];
}

// ---------------- preprocessing ----------------------------------------------
__global__ void zero_cnt_kernel() {
    int i = blockIdx.x * blockDim.x + threadIdx.x;
    if (i < N_NODES) g_cnt[i] = 0;
}

__global__ void count_kernel(const void* __restrict__ ei) {
    int e = blockIdx.x * blockDim.x + threadIdx.x;
    if (e < N_EDGES) {
        int d = load_idx(ei, (long)N_EDGES + e);
        atomicAdd(&g_cnt[d], 1);
    }
}

__global__ void dinv_kernel() {
    int i = blockIdx.x * blockDim.x + threadIdx.x;
    if (i < N_NODES) g_dinv[i] = rsqrtf((float)(g_cnt[i] + 1));  // +1 self loop
}

// one-block exclusive scan of g_cnt -> g_rowstart / g_cursor
__global__ void scan_kernel() {
    __shared__ int part[1024];
    int t = threadIdx.x;
    const int SEG = (N_NODES + 1023) / 1024;  // 49
    int beg = t * SEG;
    int end = beg + SEG; if (end > N_NODES) end = N_NODES;
    int s = 0;
    for (int i = beg; i < end; i++) s += g_cnt[i];
    part[t] = s;
    __syncthreads();
    for (int d = 1; d < 1024; d <<= 1) {
        int add = (t >= d) ? part[t - d] : 0;
        __syncthreads();
        part[t] += add;
        __syncthreads();
    }
    int off = (t == 0) ? 0 : part[t - 1];
    for (int i = beg; i < end; i++) {
        g_rowstart[i] = off;
        g_cursor[i]   = off;
        off += g_cnt[i];
    }
    if (t == 1023) g_rowstart[N_NODES] = part[1023];
}

__global__ void scatter_kernel(const void* __restrict__ ei) {
    int e = blockIdx.x * blockDim.x + threadIdx.x;
    if (e < N_EDGES) {
        int s = load_idx(ei, e);
        int d = load_idx(ei, (long)N_EDGES + e);
        int pos = atomicAdd(&g_cursor[d], 1);
        g_col[pos] = s;
        g_val[pos] = g_dinv[s] * g_dinv[d];
    }
}

// ---------------- GEMM: h0[50000,64] = X[50000,256] @ W[256,64] --------------
// block = 256 threads, tile 64 rows x 64 cols, BK = 16, thread tile 4x4.
__global__ __launch_bounds__(256) void gemm_kernel(
    const float* __restrict__ X, const float* __restrict__ W
) {
    __shared__ __align__(16) float As[16][64];   // [k][row]
    __shared__ __align__(16) float Bs[16 * 64];  // [k][col] (linear, matches W)
    int tid  = threadIdx.x;
    int row0 = blockIdx.x * 64;
    int ty = tid >> 4;   // 0..15 -> rows ty*4 .. ty*4+3
    int tx = tid & 15;   // 0..15 -> cols tx*4 .. tx*4+3

    float acc[4][4] = {};
    // A-tile load mapping: one float4 along K per thread
    int lr = tid >> 2;          // 0..63 local row
    int lk = (tid & 3) * 4;     // 0,4,8,12
    int grow = row0 + lr;
    bool rvalid = grow < N_NODES;
    const float* xptr = X + (size_t)grow * N_FEAT + lk;

    for (int k0 = 0; k0 < N_FEAT; k0 += 16) {
        float4 xv = make_float4(0.f, 0.f, 0.f, 0.f);
        if (rvalid) xv = *(const float4*)(xptr + k0);
        As[lk + 0][lr] = xv.x;
        As[lk + 1][lr] = xv.y;
        As[lk + 2][lr] = xv.z;
        As[lk + 3][lr] = xv.w;
        // W chunk [k0..k0+16) x 64 is 1024 contiguous floats
        *(float4*)&Bs[tid * 4] = *(const float4*)&W[(size_t)k0 * 64 + tid * 4];
        __syncthreads();
        #pragma unroll
        for (int kk = 0; kk < 16; kk++) {
            float4 a = *(const float4*)&As[kk][ty * 4];
            float4 b = *(const float4*)&Bs[kk * 64 + tx * 4];
            acc[0][0] = fmaf(a.x, b.x, acc[0][0]);
            acc[0][1] = fmaf(a.x, b.y, acc[0][1]);
            acc[0][2] = fmaf(a.x, b.z, acc[0][2]);
            acc[0][3] = fmaf(a.x, b.w, acc[0][3]);
            acc[1][0] = fmaf(a.y, b.x, acc[1][0]);
            acc[1][1] = fmaf(a.y, b.y, acc[1][1]);
            acc[1][2] = fmaf(a.y, b.z, acc[1][2]);
            acc[1][3] = fmaf(a.y, b.w, acc[1][3]);
            acc[2][0] = fmaf(a.z, b.x, acc[2][0]);
            acc[2][1] = fmaf(a.z, b.y, acc[2][1]);
            acc[2][2] = fmaf(a.z, b.z, acc[2][2]);
            acc[2][3] = fmaf(a.z, b.w, acc[2][3]);
            acc[3][0] = fmaf(a.w, b.x, acc[3][0]);
            acc[3][1] = fmaf(a.w, b.y, acc[3][1]);
            acc[3][2] = fmaf(a.w, b.z, acc[3][2]);
            acc[3][3] = fmaf(a.w, b.w, acc[3][3]);
        }
        __syncthreads();
    }
    #pragma unroll
    for (int i = 0; i < 4; i++) {
        int r = row0 + ty * 4 + i;
        if (r < N_NODES) {
            float4 o = make_float4(acc[i][0], acc[i][1], acc[i][2], acc[i][3]);
            *(float4*)&g_h0[(size_t)r * 64 + tx * 4] = o;
        }
    }
}

// ---------------- propagation hop: warp per node, float2 per lane ------------
// hout[n] = selfc(n)*hin[n] + sum_{e: dst==n} val[e]*hin[col[e]]  (+bias last)
__global__ __launch_bounds__(256) void hop_kernel(
    int sel_in, int sel_out, const float* __restrict__ bias, float* __restrict__ dout
) {
    int warp = (blockIdx.x * blockDim.x + threadIdx.x) >> 5;
    int lane = threadIdx.x & 31;
    if (warp >= N_NODES) return;
    int n = warp;

    const float* hin = (sel_in == 0) ? g_h0 : g_h1;
    float* hout = (sel_out == 0) ? g_h0 : ((sel_out == 1) ? g_h1 : dout);

    float di = g_dinv[n];
    float selfc = di * di;

    const float2* hin2 = (const float2*)hin;
    float2 hv = hin2[(size_t)n * 32 + lane];
    float2 acc = make_float2(selfc * hv.x, selfc * hv.y);

    int start = g_rowstart[n];
    int end   = g_rowstart[n + 1];
    for (int base = start; base < end; base += 32) {
        int idx = base + lane;
        int c = 0; float w = 0.f;
        if (idx < end) { c = g_col[idx]; w = g_val[idx]; }
        int m = end - base; if (m > 32) m = 32;
        #pragma unroll 4
        for (int j = 0; j < m; j++) {
            int   s  = __shfl_sync(0xffffffffu, c, j);
            float ww = __shfl_sync(0xffffffffu, w, j);
            float2 v = hin2[(size_t)s * 32 + lane];
            acc.x = fmaf(ww, v.x, acc.x);
            acc.y = fmaf(ww, v.y, acc.y);
        }
    }
    if (bias) {
        float2 bb = ((const float2*)bias)[lane];
        acc.x += bb.x;
        acc.y += bb.y;
    }
    ((float2*)hout)[(size_t)n * 32 + lane] = acc;
}

// ---------------- launch ------------------------------------------------------
extern "C" void kernel_launch(void* const* d_in, const int* in_sizes, int n_in,
                              void* d_out, int out_size) {
    const float* x  = (const float*)d_in[0];
    const void*  ei = d_in[1];
    const float* W  = (const float*)d_in[2];
    const float* b  = (const float*)d_in[3];
    float* out = (float*)d_out;

    const int TB = 256;
    detect_kernel<<<1, 1>>>(ei);
    zero_cnt_kernel<<<(N_NODES + TB - 1) / TB, TB>>>();
    count_kernel<<<(N_EDGES + TB - 1) / TB, TB>>>(ei);
    dinv_kernel<<<(N_NODES + TB - 1) / TB, TB>>>();
    scan_kernel<<<1, 1024>>>();
    scatter_kernel<<<(N_EDGES + TB - 1) / TB, TB>>>(ei);

    // project first (S^3 x) W == S^3 (x W): 4x less hop traffic
    gemm_kernel<<<(N_NODES + 63) / 64, TB>>>(x, W);

    int hop_blocks = (N_NODES * 32 + TB - 1) / TB;  // warp per node
    hop_kernel<<<hop_blocks, TB>>>(0, 1, nullptr, nullptr);
    hop_kernel<<<hop_blocks, TB>>>(1, 0, nullptr, nullptr);
    hop_kernel<<<hop_blocks, TB>>>(0, 2, b, out);
}